// round 4
// baseline (speedup 1.0000x reference)
#include <cuda_runtime.h>
#include <cstdint>

#define C_ 128
#define F_ 1024
#define BK 32
#define NCHUNK (F_/BK)
#define NTHREADS 256
#define APITCH 36                    // pad: bank = (4g + tig) % 32, conflict-free fragments
#define A_FLOATS (128*APITCH)
#define B_FLOATS (64*APITCH)
#define SMEM_FLOATS (2*A_FLOATS + 2*B_FLOATS)
#define SMEM_BYTES (SMEM_FLOATS*4)   // 55296

__device__ __forceinline__ uint32_t tf32r(float v) {
    uint32_t r;
    asm("cvt.rna.tf32.f32 %0, %1;" : "=r"(r) : "f"(v));
    return r;
}

__device__ __forceinline__ void mma_tf32(float d[4], const uint32_t a[4], const uint32_t b[2]) {
    asm volatile(
        "mma.sync.aligned.m16n8k8.row.col.f32.tf32.tf32.f32 "
        "{%0,%1,%2,%3}, {%4,%5,%6,%7}, {%8,%9}, {%0,%1,%2,%3};"
        : "+f"(d[0]), "+f"(d[1]), "+f"(d[2]), "+f"(d[3])
        : "r"(a[0]), "r"(a[1]), "r"(a[2]), "r"(a[3]), "r"(b[0]), "r"(b[1]));
}

__device__ __forceinline__ void sts4(float* p, float4 v) {
    uint32_t x0 = tf32r(v.x), x1 = tf32r(v.y), x2 = tf32r(v.z), x3 = tf32r(v.w);
    uint4* q = reinterpret_cast<uint4*>(p);
    *q = make_uint4(x0, x1, x2, x3);
}

__global__ void __launch_bounds__(NTHREADS, 2) cwlinear_mma_kernel(
    const float* __restrict__ x, const float* __restrict__ W,
    const float* __restrict__ bias, float* __restrict__ out)
{
    extern __shared__ float sm[];
    const int tid = threadIdx.x;
    const int wid = tid >> 5, lid = tid & 31;
    const int wm = wid >> 1, wn = wid & 1;          // warp grid 4 (m) x 2 (n)
    const int g = lid >> 2, tig = lid & 3;          // quad layout
    const int gt = blockIdx.x;                      // 0..7 g-tile
    const int c  = blockIdx.y;                      // 0..127 channel
    const int g0 = gt * 128;

    // ---- per-thread STS/gmem mapping (constant per chunk) ----
    const float* Wg = W + ((size_t)c * F_ + g0) * F_;
    const float* a_g[4]; int a_so[4];
#pragma unroll
    for (int i = 0; i < 4; i++) {
        int f4 = tid + i * NTHREADS;                // 0..1023 : 128 rows x 8 float4
        int r = f4 >> 3, c4 = f4 & 7;
        a_so[i] = r * APITCH + c4 * 4;
        a_g[i]  = Wg + (size_t)r * F_ + c4 * 4;
    }
    const float* b_g[2]; int b_so[2];
#pragma unroll
    for (int i = 0; i < 2; i++) {
        int f4 = tid + i * NTHREADS;                // 0..511 : 64 rows x 8 float4
        int r = f4 >> 3, c4 = f4 & 7;
        b_so[i] = r * APITCH + c4 * 4;
        b_g[i]  = x + ((size_t)r * C_ + c) * F_ + c4 * 4;
    }

    float d[2][4][4];
#pragma unroll
    for (int mt = 0; mt < 2; mt++)
#pragma unroll
        for (int nt = 0; nt < 4; nt++)
#pragma unroll
            for (int j = 0; j < 4; j++) d[mt][nt][j] = 0.0f;

    // ---- prologue prefetch (chunk 0) ----
    float4 ra[4], rb[2];
#pragma unroll
    for (int i = 0; i < 4; i++) ra[i] = __ldcs((const float4*)a_g[i]);   // W: evict-first
#pragma unroll
    for (int i = 0; i < 2; i++) rb[i] = __ldg((const float4*)b_g[i]);    // x: L2-resident

    // fragment base offsets (float indices), constant across chunks
    const int afrag0 = (wm * 32 + g) * APITCH + tig;          // mt=0 ; +16*APITCH for mt=1
    const int bfrag0 = (wn * 32 + g) * APITCH + tig;          // nt=0 ; +8*APITCH per nt

    for (int kc = 0; kc < NCHUNK; kc++) {
        const int buf = kc & 1;
        float* Ab = sm + buf * A_FLOATS;
        float* Bb = sm + 2 * A_FLOATS + buf * B_FLOATS;

#pragma unroll
        for (int i = 0; i < 4; i++) sts4(Ab + a_so[i], ra[i]);
#pragma unroll
        for (int i = 0; i < 2; i++) sts4(Bb + b_so[i], rb[i]);
        __syncthreads();

        if (kc + 1 < NCHUNK) {
            const int off = (kc + 1) * BK;
#pragma unroll
            for (int i = 0; i < 4; i++) ra[i] = __ldcs((const float4*)(a_g[i] + off));
#pragma unroll
            for (int i = 0; i < 2; i++) rb[i] = __ldg((const float4*)(b_g[i] + off));
        }

#pragma unroll
        for (int s = 0; s < 4; s++) {
            const int ks = s * 8;
            uint32_t af[2][4];
#pragma unroll
            for (int mt = 0; mt < 2; mt++) {
                const float* ap = Ab + afrag0 + mt * 16 * APITCH + ks;
                af[mt][0] = __float_as_uint(ap[0]);
                af[mt][1] = __float_as_uint(ap[8 * APITCH]);
                af[mt][2] = __float_as_uint(ap[4]);
                af[mt][3] = __float_as_uint(ap[8 * APITCH + 4]);
            }
            uint32_t bf[4][2];
#pragma unroll
            for (int nt = 0; nt < 4; nt++) {
                const float* bp = Bb + bfrag0 + nt * 8 * APITCH + ks;
                bf[nt][0] = __float_as_uint(bp[0]);
                bf[nt][1] = __float_as_uint(bp[4]);
            }
#pragma unroll
            for (int mt = 0; mt < 2; mt++)
#pragma unroll
                for (int nt = 0; nt < 4; nt++)
                    mma_tf32(d[mt][nt], af[mt], bf[nt]);
        }
    }

    // ---- epilogue: y[b, c, g] = d + bias[c, g] ----
#pragma unroll
    for (int mt = 0; mt < 2; mt++) {
        const int m0 = g0 + wm * 32 + mt * 16 + g;            // g row (c0/c1)
        const float bv0 = bias[c * F_ + m0];
        const float bv1 = bias[c * F_ + m0 + 8];
#pragma unroll
        for (int nt = 0; nt < 4; nt++) {
            const int n0 = wn * 32 + nt * 8 + 2 * tig;        // batch col
            float* o0 = out + ((size_t)n0 * C_ + c) * F_;
            float* o1 = o0 + (size_t)C_ * F_;                 // batch n0+1
            o0[m0]     = d[mt][nt][0] + bv0;
            o1[m0]     = d[mt][nt][1] + bv0;
            o0[m0 + 8] = d[mt][nt][2] + bv1;
            o1[m0 + 8] = d[mt][nt][3] + bv1;
        }
    }
}

extern "C" void kernel_launch(void* const* d_in, const int* in_sizes, int n_in,
                              void* d_out, int out_size) {
    const float* x    = (const float*)d_in[0];
    const float* W    = (const float*)d_in[1];
    const float* bias = (const float*)d_in[2];
    float* out = (float*)d_out;

    cudaFuncSetAttribute(cwlinear_mma_kernel,
                         cudaFuncAttributeMaxDynamicSharedMemorySize, SMEM_BYTES);
    cwlinear_mma_kernel<<<dim3(8, C_), NTHREADS, SMEM_BYTES>>>(x, W, bias, out);
}